// round 2
// baseline (speedup 1.0000x reference)
#include <cuda_runtime.h>

// Problem constants (fixed by the dataset)
#define BATCH 4
#define SEQ   2048
#define DIM   1024
#define QKV_LD (3 * DIM)   // 3072

// ---------------- scratch (allocation-free: device globals) ----------------
__device__ float g_qkv[(long)BATCH * SEQ * 3 * DIM];      // [B,S,3*DIM]
__device__ float g_scores[(long)BATCH * SEQ * SEQ];       // [B,S,S]
__device__ float g_attnout[(long)BATCH * SEQ * DIM];      // [B,S,DIM]

// ---------------- tiled SGEMM params ----------------
#define BM 128
#define BN 128
#define BK 8
#define TM 8
#define TN 8
// 256 threads: 16x16 thread grid, each computes 8x8 (split 4+4 to avoid
// smem bank conflicts on the Bs/As vector loads)

// C[M,N] = A[M,K] * B[N,K]^T (+bias), A/B row-major with leading dims lda/ldb.
// Batched via blockIdx.z with element strides. No bounds checks: all shapes
// used here are multiples of 128 (M,N) and 8 (K).
__global__ __launch_bounds__(256)
void gemm_nt(const float* __restrict__ A, const float* __restrict__ B,
             const float* __restrict__ bias, float* __restrict__ C,
             int K, int lda, int ldb, int ldc,
             long strideA, long strideB, long strideC)
{
    __shared__ float As[BK][BM];
    __shared__ float Bs[BK][BN];

    A += (long)blockIdx.z * strideA + (long)blockIdx.y * BM * lda;
    B += (long)blockIdx.z * strideB + (long)blockIdx.x * BN * ldb;
    C += (long)blockIdx.z * strideC + (long)blockIdx.y * BM * ldc + (long)blockIdx.x * BN;

    const int t  = threadIdx.x;
    const int tx = t & 15;       // 0..15 -> N
    const int ty = t >> 4;       // 0..15 -> M
    const int lrow = t >> 1;     // 0..127 (row loaded)
    const int lk   = (t & 1) * 4; // 0 or 4

    float acc[TM][TN];
    #pragma unroll
    for (int i = 0; i < TM; i++)
        #pragma unroll
        for (int j = 0; j < TN; j++) acc[i][j] = 0.0f;

    for (int k0 = 0; k0 < K; k0 += BK) {
        float4 va = *(const float4*)&A[(long)lrow * lda + k0 + lk];
        float4 vb = *(const float4*)&B[(long)lrow * ldb + k0 + lk];
        As[lk + 0][lrow] = va.x; As[lk + 1][lrow] = va.y;
        As[lk + 2][lrow] = va.z; As[lk + 3][lrow] = va.w;
        Bs[lk + 0][lrow] = vb.x; Bs[lk + 1][lrow] = vb.y;
        Bs[lk + 2][lrow] = vb.z; Bs[lk + 3][lrow] = vb.w;
        __syncthreads();

        #pragma unroll
        for (int kk = 0; kk < BK; kk++) {
            float a[TM], b[TN];
            float4 a0 = *(const float4*)&As[kk][ty * 4];
            float4 a1 = *(const float4*)&As[kk][64 + ty * 4];
            float4 b0 = *(const float4*)&Bs[kk][tx * 4];
            float4 b1 = *(const float4*)&Bs[kk][64 + tx * 4];
            a[0]=a0.x; a[1]=a0.y; a[2]=a0.z; a[3]=a0.w;
            a[4]=a1.x; a[5]=a1.y; a[6]=a1.z; a[7]=a1.w;
            b[0]=b0.x; b[1]=b0.y; b[2]=b0.z; b[3]=b0.w;
            b[4]=b1.x; b[5]=b1.y; b[6]=b1.z; b[7]=b1.w;
            #pragma unroll
            for (int i = 0; i < TM; i++)
                #pragma unroll
                for (int j = 0; j < TN; j++)
                    acc[i][j] += a[i] * b[j];
        }
        __syncthreads();
    }

    #pragma unroll
    for (int i = 0; i < TM; i++) {
        int row = (i < 4) ? (ty * 4 + i) : (64 + ty * 4 + (i - 4));
        #pragma unroll
        for (int j = 0; j < TN; j++) {
            int col = (j < 4) ? (tx * 4 + j) : (64 + tx * 4 + (j - 4));
            float bv = bias ? bias[(long)blockIdx.x * BN + col] : 0.0f;
            C[(long)row * ldc + col] = acc[i][j] + bv;
        }
    }
}

// C[M,N] = A[M,K] * B[K,N], both row-major (NN). Used for attn @ V.
__global__ __launch_bounds__(256)
void gemm_nn(const float* __restrict__ A, const float* __restrict__ B,
             float* __restrict__ C,
             int K, int lda, int ldb, int ldc,
             long strideA, long strideB, long strideC)
{
    __shared__ float As[BK][BM];
    __shared__ float Bs[BK][BN];

    A += (long)blockIdx.z * strideA + (long)blockIdx.y * BM * lda;
    B += (long)blockIdx.z * strideB + (long)blockIdx.x * BN;
    C += (long)blockIdx.z * strideC + (long)blockIdx.y * BM * ldc + (long)blockIdx.x * BN;

    const int t  = threadIdx.x;
    const int tx = t & 15;
    const int ty = t >> 4;
    const int lrow = t >> 1;       // A load: row
    const int lk   = (t & 1) * 4;  // A load: k offset
    const int bk   = t >> 5;       // B load: k row (0..7)
    const int bn   = (t & 31) * 4; // B load: n offset (0..124)

    float acc[TM][TN];
    #pragma unroll
    for (int i = 0; i < TM; i++)
        #pragma unroll
        for (int j = 0; j < TN; j++) acc[i][j] = 0.0f;

    for (int k0 = 0; k0 < K; k0 += BK) {
        float4 va = *(const float4*)&A[(long)lrow * lda + k0 + lk];
        As[lk + 0][lrow] = va.x; As[lk + 1][lrow] = va.y;
        As[lk + 2][lrow] = va.z; As[lk + 3][lrow] = va.w;
        float4 vb = *(const float4*)&B[(long)(k0 + bk) * ldb + bn];
        *(float4*)&Bs[bk][bn] = vb;
        __syncthreads();

        #pragma unroll
        for (int kk = 0; kk < BK; kk++) {
            float a[TM], b[TN];
            float4 a0 = *(const float4*)&As[kk][ty * 4];
            float4 a1 = *(const float4*)&As[kk][64 + ty * 4];
            float4 b0 = *(const float4*)&Bs[kk][tx * 4];
            float4 b1 = *(const float4*)&Bs[kk][64 + tx * 4];
            a[0]=a0.x; a[1]=a0.y; a[2]=a0.z; a[3]=a0.w;
            a[4]=a1.x; a[5]=a1.y; a[6]=a1.z; a[7]=a1.w;
            b[0]=b0.x; b[1]=b0.y; b[2]=b0.z; b[3]=b0.w;
            b[4]=b1.x; b[5]=b1.y; b[6]=b1.z; b[7]=b1.w;
            #pragma unroll
            for (int i = 0; i < TM; i++)
                #pragma unroll
                for (int j = 0; j < TN; j++)
                    acc[i][j] += a[i] * b[j];
        }
        __syncthreads();
    }

    #pragma unroll
    for (int i = 0; i < TM; i++) {
        int row = (i < 4) ? (ty * 4 + i) : (64 + ty * 4 + (i - 4));
        #pragma unroll
        for (int j = 0; j < TN; j++) {
            int col = (j < 4) ? (tx * 4 + j) : (64 + tx * 4 + (j - 4));
            C[(long)row * ldc + col] = acc[i][j];
        }
    }
}

// Masked, scaled softmax over the last axis of scores [B,S,S], in place.
// Matches reference: mask applied to RAW scores (-1e20), THEN /sqrt(DIM), then softmax.
__global__ __launch_bounds__(256)
void softmax_kernel(float* __restrict__ scores, const int* __restrict__ mask)
{
    const int b = blockIdx.y;
    const int q = blockIdx.x;
    float* row = scores + ((long)b * SEQ + q) * SEQ;
    const int* m = mask + (long)b * SEQ;   // mask is [B,1,S]
    const int t = threadIdx.x;
    const float scale = 0.03125f;          // 1/sqrt(1024)

    __shared__ float red[256];

    float mx = -3.4e38f;
    for (int k = t; k < SEQ; k += 256) {
        float v = row[k];
        v = (m[k] == 0) ? -1e20f : v;
        v *= scale;
        row[k] = v;
        mx = fmaxf(mx, v);
    }
    red[t] = mx;
    __syncthreads();
    for (int s = 128; s > 0; s >>= 1) {
        if (t < s) red[t] = fmaxf(red[t], red[t + s]);
        __syncthreads();
    }
    mx = red[0];
    __syncthreads();

    float sum = 0.0f;
    for (int k = t; k < SEQ; k += 256) {
        float e = __expf(row[k] - mx);
        row[k] = e;
        sum += e;
    }
    red[t] = sum;
    __syncthreads();
    for (int s = 128; s > 0; s >>= 1) {
        if (t < s) red[t] += red[t + s];
        __syncthreads();
    }
    float inv = 1.0f / red[0];
    for (int k = t; k < SEQ; k += 256) row[k] *= inv;
}

extern "C" void kernel_launch(void* const* d_in, const int* in_sizes, int n_in,
                              void* d_out, int out_size)
{
    const float* X     = (const float*)d_in[0];  // [B,S,DIM]
    const int*   amask = (const int*)  d_in[1];  // [B,1,S]
    const float* W_in  = (const float*)d_in[2];  // [3*DIM, DIM]
    const float* b_in  = (const float*)d_in[3];  // [3*DIM]
    const float* W_out = (const float*)d_in[4];  // [DIM, DIM]
    const float* b_out = (const float*)d_in[5];  // [DIM]
    float* out = (float*)d_out;                  // [B,S,DIM]

    float *qkv, *scores, *attnout;
    cudaGetSymbolAddress((void**)&qkv,     g_qkv);
    cudaGetSymbolAddress((void**)&scores,  g_scores);
    cudaGetSymbolAddress((void**)&attnout, g_attnout);

    dim3 block(256);

    // 1) QKV projection: [8192,3072] = X[8192,1024] @ W_in^T + b_in
    {
        dim3 grid(3 * DIM / BN, BATCH * SEQ / BM, 1);
        gemm_nt<<<grid, block>>>(X, W_in, b_in, qkv,
                                 DIM, DIM, DIM, QKV_LD, 0, 0, 0);
    }

    // 2) scores[b] = Q[b] @ K[b]^T  (per batch, M=N=2048, K=1024)
    {
        dim3 grid(SEQ / BN, SEQ / BM, BATCH);
        gemm_nt<<<grid, block>>>(qkv /*Q at offset 0*/, qkv + DIM /*K*/,
                                 nullptr, scores,
                                 DIM, QKV_LD, QKV_LD, SEQ,
                                 (long)SEQ * QKV_LD, (long)SEQ * QKV_LD,
                                 (long)SEQ * SEQ);
    }

    // 3) masked + scaled softmax (in place on scores)
    {
        dim3 grid(SEQ, BATCH);
        softmax_kernel<<<grid, block>>>(scores, amask);
    }

    // 4) attn @ V  (per batch, M=2048, N=1024, K=2048)
    {
        dim3 grid(DIM / BN, SEQ / BM, BATCH);
        gemm_nn<<<grid, block>>>(scores, qkv + 2 * DIM /*V*/, attnout,
                                 SEQ, SEQ, QKV_LD, DIM,
                                 (long)SEQ * SEQ, (long)SEQ * QKV_LD,
                                 (long)SEQ * DIM);
    }

    // 5) output projection: [8192,1024] = attnout @ W_out^T + b_out
    {
        dim3 grid(DIM / BN, BATCH * SEQ / BM, 1);
        gemm_nt<<<grid, block>>>(attnout, W_out, b_out, out,
                                 DIM, DIM, DIM, DIM, 0, 0, 0);
    }
}

// round 3
// speedup vs baseline: 4.7110x; 4.7110x over previous
#include <cuda_runtime.h>

// Problem constants
#define BATCH 4
#define SEQ   2048
#define DIM   1024
#define QKV_LD 3072

// ---------------- scratch (device globals, allocation-free) ----------------
__device__ float g_qkv[(long)BATCH * SEQ * 3 * DIM];   // [B,S,3*DIM]
__device__ float g_scores[(long)BATCH * SEQ * SEQ];    // [B,S,S]
__device__ float g_attnout[(long)BATCH * SEQ * DIM];   // [B,S,DIM]
__device__ float g_vt[(long)BATCH * DIM * SEQ];        // [B,DIM,SEQ] (V transposed)

// ---------------- tensor-core tile params ----------------
#define BM 128
#define BN 128
#define BK 32
#define PAD 36   // smem row stride (floats): makes tile STS.128 and all
                 // fragment LDS.32 reads bank-conflict-free (bank = 4g+c)

__device__ __forceinline__ float f2tf32(float x) {
    unsigned r;
    asm("cvt.rna.tf32.f32 %0, %1;" : "=r"(r) : "f"(x));
    return __uint_as_float(r);
}

// C[M,N] = A[M,K] * B[N,K]^T (+bias). Row-major A/B. Batched via blockIdx.z.
// M,N multiples of 128; K multiple of 32. tf32 tensor-core mma.
__global__ __launch_bounds__(256, 2)
void gemm_nt_tc(const float* __restrict__ A, const float* __restrict__ B,
                const float* __restrict__ bias, float* __restrict__ C,
                int K, int lda, int ldb, int ldc,
                long sA, long sB, long sC)
{
    __shared__ float As[BM][PAD];
    __shared__ float Bs[BN][PAD];

    A += (long)blockIdx.z * sA + (long)blockIdx.y * BM * lda;
    B += (long)blockIdx.z * sB + (long)blockIdx.x * BN * ldb;
    C += (long)blockIdx.z * sC + (long)blockIdx.y * BM * ldc + (long)blockIdx.x * BN;

    const int t    = threadIdx.x;
    const int warp = t >> 5;
    const int lane = t & 31;
    const int g    = lane >> 2;   // groupID 0..7
    const int c4   = lane & 3;    // threadID_in_group 0..3
    const int wm   = (warp >> 2) * 64;   // warp M offset: 0 / 64
    const int wn   = (warp & 3) * 32;    // warp N offset: 0/32/64/96

    float acc[4][4][4];
    #pragma unroll
    for (int mi = 0; mi < 4; mi++)
        #pragma unroll
        for (int ni = 0; ni < 4; ni++)
            #pragma unroll
            for (int r = 0; r < 4; r++) acc[mi][ni][r] = 0.0f;

    for (int k0 = 0; k0 < K; k0 += BK) {
        // ---- load 128x32 tiles of A and B into smem (tf32-rounded) ----
        #pragma unroll
        for (int i = 0; i < 4; i++) {
            int f  = t + i * 256;        // 0..1023
            int r  = f >> 3;             // row 0..127
            int kg = (f & 7) * 4;        // k offset 0,4,..,28
            float4 va = *(const float4*)&A[(long)r * lda + k0 + kg];
            float4 vb = *(const float4*)&B[(long)r * ldb + k0 + kg];
            va.x = f2tf32(va.x); va.y = f2tf32(va.y);
            va.z = f2tf32(va.z); va.w = f2tf32(va.w);
            vb.x = f2tf32(vb.x); vb.y = f2tf32(vb.y);
            vb.z = f2tf32(vb.z); vb.w = f2tf32(vb.w);
            *(float4*)&As[r][kg] = va;
            *(float4*)&Bs[r][kg] = vb;
        }
        __syncthreads();

        // ---- 4 k-substeps of 8 ----
        #pragma unroll
        for (int ks = 0; ks < 4; ks++) {
            const int kk = ks * 8;
            unsigned a[4][4], b[4][2];
            #pragma unroll
            for (int mi = 0; mi < 4; mi++) {
                int rb = wm + mi * 16;
                a[mi][0] = __float_as_uint(As[rb + g    ][kk + c4    ]);
                a[mi][1] = __float_as_uint(As[rb + g + 8][kk + c4    ]);
                a[mi][2] = __float_as_uint(As[rb + g    ][kk + c4 + 4]);
                a[mi][3] = __float_as_uint(As[rb + g + 8][kk + c4 + 4]);
            }
            #pragma unroll
            for (int ni = 0; ni < 4; ni++) {
                int cb = wn + ni * 8;
                b[ni][0] = __float_as_uint(Bs[cb + g][kk + c4    ]);
                b[ni][1] = __float_as_uint(Bs[cb + g][kk + c4 + 4]);
            }
            #pragma unroll
            for (int mi = 0; mi < 4; mi++)
                #pragma unroll
                for (int ni = 0; ni < 4; ni++) {
                    asm volatile(
                        "mma.sync.aligned.m16n8k8.row.col.f32.tf32.tf32.f32 "
                        "{%0,%1,%2,%3}, {%4,%5,%6,%7}, {%8,%9}, {%0,%1,%2,%3};"
                        : "+f"(acc[mi][ni][0]), "+f"(acc[mi][ni][1]),
                          "+f"(acc[mi][ni][2]), "+f"(acc[mi][ni][3])
                        : "r"(a[mi][0]), "r"(a[mi][1]), "r"(a[mi][2]), "r"(a[mi][3]),
                          "r"(b[ni][0]), "r"(b[ni][1]));
                }
        }
        __syncthreads();
    }

    // ---- epilogue ----
    #pragma unroll
    for (int mi = 0; mi < 4; mi++) {
        #pragma unroll
        for (int ni = 0; ni < 4; ni++) {
            int row = wm + mi * 16 + g;
            int col = wn + ni * 8 + c4 * 2;
            float bv0 = 0.0f, bv1 = 0.0f;
            if (bias) {
                bv0 = bias[(long)blockIdx.x * BN + col];
                bv1 = bias[(long)blockIdx.x * BN + col + 1];
            }
            float2 v0 = make_float2(acc[mi][ni][0] + bv0, acc[mi][ni][1] + bv1);
            float2 v1 = make_float2(acc[mi][ni][2] + bv0, acc[mi][ni][3] + bv1);
            *(float2*)&C[(long)row * ldc + col]       = v0;
            *(float2*)&C[(long)(row + 8) * ldc + col] = v1;
        }
    }
}

// Transpose V (cols [2*DIM,3*DIM) of qkv) per batch: Vt[b][d][s] = V[b][s][d]
__global__ __launch_bounds__(256)
void transpose_v(const float* __restrict__ qkv, float* __restrict__ vt)
{
    __shared__ float tile[32][33];
    const int b  = blockIdx.z;
    const int s0 = blockIdx.x * 32;
    const int d0 = blockIdx.y * 32;
    const int tx = threadIdx.x & 31;
    const int ty = threadIdx.x >> 5;   // 0..7

    const float* V = qkv + (long)b * SEQ * QKV_LD + 2 * DIM;
    #pragma unroll
    for (int i = 0; i < 4; i++)
        tile[ty + 8 * i][tx] = V[(long)(s0 + ty + 8 * i) * QKV_LD + d0 + tx];
    __syncthreads();

    float* out = vt + (long)b * DIM * SEQ;
    #pragma unroll
    for (int i = 0; i < 4; i++)
        out[(long)(d0 + ty + 8 * i) * SEQ + s0 + tx] = tile[tx][ty + 8 * i];
}

// Masked, scaled softmax over last axis of scores [B,S,S], in place.
// Mask applied to RAW scores (-1e20), THEN /sqrt(DIM), then softmax.
__global__ __launch_bounds__(256)
void softmax_kernel(float* __restrict__ scores, const int* __restrict__ mask)
{
    const int b = blockIdx.y;
    const int q = blockIdx.x;
    float* row = scores + ((long)b * SEQ + q) * SEQ;
    const int* m = mask + (long)b * SEQ;
    const int t = threadIdx.x;
    const float scale = 0.03125f;   // 1/sqrt(1024)

    __shared__ float red[256];

    float mx = -3.4e38f;
    for (int k = t; k < SEQ; k += 256) {
        float v = row[k];
        v = (m[k] == 0) ? -1e20f : v;
        v *= scale;
        row[k] = v;
        mx = fmaxf(mx, v);
    }
    red[t] = mx;
    __syncthreads();
    for (int s = 128; s > 0; s >>= 1) {
        if (t < s) red[t] = fmaxf(red[t], red[t + s]);
        __syncthreads();
    }
    mx = red[0];
    __syncthreads();

    float sum = 0.0f;
    for (int k = t; k < SEQ; k += 256) {
        float e = __expf(row[k] - mx);
        row[k] = e;
        sum += e;
    }
    red[t] = sum;
    __syncthreads();
    for (int s = 128; s > 0; s >>= 1) {
        if (t < s) red[t] += red[t + s];
        __syncthreads();
    }
    float inv = 1.0f / red[0];
    for (int k = t; k < SEQ; k += 256) row[k] *= inv;
}

extern "C" void kernel_launch(void* const* d_in, const int* in_sizes, int n_in,
                              void* d_out, int out_size)
{
    const float* X     = (const float*)d_in[0];  // [B,S,DIM]
    const int*   amask = (const int*)  d_in[1];  // [B,1,S]
    const float* W_in  = (const float*)d_in[2];  // [3*DIM, DIM]
    const float* b_in  = (const float*)d_in[3];  // [3*DIM]
    const float* W_out = (const float*)d_in[4];  // [DIM, DIM]
    const float* b_out = (const float*)d_in[5];  // [DIM]
    float* out = (float*)d_out;                  // [B,S,DIM]

    float *qkv, *scores, *attnout, *vt;
    cudaGetSymbolAddress((void**)&qkv,     g_qkv);
    cudaGetSymbolAddress((void**)&scores,  g_scores);
    cudaGetSymbolAddress((void**)&attnout, g_attnout);
    cudaGetSymbolAddress((void**)&vt,      g_vt);

    dim3 block(256);

    // 1) QKV projection: [8192,3072] = X @ W_in^T + b_in
    {
        dim3 grid(3 * DIM / BN, BATCH * SEQ / BM, 1);
        gemm_nt_tc<<<grid, block>>>(X, W_in, b_in, qkv,
                                    DIM, DIM, DIM, QKV_LD, 0, 0, 0);
    }

    // 2) transpose V into Vt [B,DIM,SEQ]
    {
        dim3 grid(SEQ / 32, DIM / 32, BATCH);
        transpose_v<<<grid, block>>>(qkv, vt);
    }

    // 3) scores[b] = Q[b] @ K[b]^T  (M=N=2048, K=1024)
    {
        dim3 grid(SEQ / BN, SEQ / BM, BATCH);
        gemm_nt_tc<<<grid, block>>>(qkv, qkv + DIM, nullptr, scores,
                                    DIM, QKV_LD, QKV_LD, SEQ,
                                    (long)SEQ * QKV_LD, (long)SEQ * QKV_LD,
                                    (long)SEQ * SEQ);
    }

    // 4) masked + scaled softmax (in place)
    {
        dim3 grid(SEQ, BATCH);
        softmax_kernel<<<grid, block>>>(scores, amask);
    }

    // 5) attn @ V == scores @ Vt^T  (M=2048, N=1024, K=2048)
    {
        dim3 grid(DIM / BN, SEQ / BM, BATCH);
        gemm_nt_tc<<<grid, block>>>(scores, vt, nullptr, attnout,
                                    SEQ, SEQ, SEQ, DIM,
                                    (long)SEQ * SEQ, (long)DIM * SEQ,
                                    (long)SEQ * DIM);
    }

    // 6) output projection: [8192,1024] = attnout @ W_out^T + b_out
    {
        dim3 grid(DIM / BN, BATCH * SEQ / BM, 1);
        gemm_nt_tc<<<grid, block>>>(attnout, W_out, b_out, out,
                                    DIM, DIM, DIM, DIM, 0, 0, 0);
    }
}